// round 15
// baseline (speedup 1.0000x reference)
#include <cuda_runtime.h>
#include <cuda_bf16.h>
#include <stdint.h>
#include <math.h>

// ---------------------------------------------------------------------------
// HierarchicalClassifier, warp-specialized bf16 HMMA on sm_103a.
// R14: MMA handles ONLY the 128 bottom columns (3-term bf16 hi/lo split);
//      the 8 top-gate columns are computed fp32-exact on the FMA pipe by
//      producer warps. 16 consumers (4Mx4N, tile 32x32, all x4-ldsm) +
//      4 producers, 3-stage XOR-swizzled pipeline, 640 threads.
// Empirical law driving this: mma.sync.f32.bf16 rate is ~1/13.7 cyc/SMSP
// regardless of warp count -> only MMA count matters. N 144->128 = -11%.
// ---------------------------------------------------------------------------

#define D_K 2048

__device__ __nv_bfloat16 g_Bh[128 * D_K];    // bottom W [n][k] K-major, bf16 hi
__device__ __nv_bfloat16 g_Bl[128 * D_K];    // bf16 lo
__device__ float         g_topWt[D_K * 8];   // topW transposed [k][t]
__device__ float         g_bias[136];        // [0,128) bottom, [128,136) top

// ---------------------------------------------------------------------------
__global__ void pack_kernel(const float* __restrict__ topW,
                            const float* __restrict__ topb,
                            const float* __restrict__ botW,
                            const float* __restrict__ botb) {
    int idx = blockIdx.x * blockDim.x + threadIdx.x;
    if (idx < 128 * D_K) {
        int n = idx / D_K, k = idx - n * D_K;
        int t = n >> 4, c = n & 15;
        float v = botW[((size_t)t * D_K + k) * 16 + c];
        __nv_bfloat16 hi = __float2bfloat16(v);
        g_Bh[idx] = hi;
        g_Bl[idx] = __float2bfloat16(v - __bfloat162float(hi));
    }
    if (idx < D_K * 8) {
        int k = idx >> 3, t = idx & 7;
        g_topWt[idx] = topW[t * D_K + k];
    }
    if (idx < 136)
        g_bias[idx] = (idx < 128) ? botb[idx] : topb[idx - 128];
}

// ---------------------------------------------------------------------------
__device__ __forceinline__ uint32_t smem_u32(const void* p) {
    uint32_t a;
    asm("{ .reg .u64 t; cvta.to.shared.u64 t, %1; cvt.u32.u64 %0, t; }"
        : "=r"(a) : "l"(p));
    return a;
}

#define LDSM_X4(r0, r1, r2, r3, addr) \
    asm volatile("ldmatrix.sync.aligned.m8n8.x4.shared.b16 {%0,%1,%2,%3}, [%4];" \
        : "=r"(r0), "=r"(r1), "=r"(r2), "=r"(r3) : "r"(addr))

#define MMA_BF16(d, a, b0, b1) \
    asm volatile("mma.sync.aligned.m16n8k16.row.col.f32.bf16.bf16.f32 " \
        "{%0,%1,%2,%3}, {%4,%5,%6,%7}, {%8,%9}, {%0,%1,%2,%3};" \
        : "+f"((d)[0]), "+f"((d)[1]), "+f"((d)[2]), "+f"((d)[3]) \
        : "r"((a)[0]), "r"((a)[1]), "r"((a)[2]), "r"((a)[3]), \
          "r"(b0), "r"(b1))

#define CP16(dst, src) \
    asm volatile("cp.async.cg.shared.global [%0], [%1], 16;" \
        :: "r"(dst), "l"(src) : "memory")
#define CP_COMMIT() asm volatile("cp.async.commit_group;" ::: "memory")
#define CP_WAIT0()  asm volatile("cp.async.wait_group 0;" ::: "memory")

#define BAR_SYNC(id)   asm volatile("bar.sync %0, 640;"   :: "r"(id) : "memory")
#define BAR_ARRIVE(id) asm volatile("bar.arrive %0, 640;" :: "r"(id) : "memory")

__device__ __forceinline__ void split2(float v0, float v1, uint32_t& h, uint32_t& l) {
    uint32_t hp;
    asm("cvt.rn.bf16x2.f32 %0, %1, %2;" : "=r"(hp) : "f"(v1), "f"(v0));
    float h0 = __uint_as_float(hp << 16);
    float h1 = __uint_as_float(hp & 0xffff0000u);
    uint32_t lp;
    asm("cvt.rn.bf16x2.f32 %0, %1, %2;" : "=r"(lp) : "f"(v1 - h1), "f"(v0 - h0));
    h = hp; l = lp;
}

// XOR swizzle: 16B unit u of a 128B row -> u ^ (row & 7)
#define SWZ16(row, u) ((uint32_t)(((u) ^ ((row) & 7)) << 4))

// ---------------------------------------------------------------------------
// Stage (pitch 128B): Ahi @0 (16384) | Alo @16384 | Bhi @32768 (16384) | Blo @49152
// STAGE = 65536, 3 stages; topL (128x8 f32 = 4096) after stage 2.
// ---------------------------------------------------------------------------
constexpr int AHI_OFF  = 0;
constexpr int ALO_OFF  = 16384;
constexpr int BHI_OFF  = 32768;
constexpr int BLO_OFF  = 49152;
constexpr int STAGE    = 65536;
constexpr int NSTAGE   = 3;
constexpr int TOPL_OFF = NSTAGE * STAGE;           // 196608
constexpr int SMEM_DYN = TOPL_OFF + 128 * 8 * 4;   // 200704

constexpr int NTHR  = 640;     // 16 consumer warps + 4 producer warps
constexpr int NCONS = 16;
constexpr int LPITCH = 128;    // logits restage pitch; 128*128*4 = 65536 = stage0

#define FULL_BAR(s) (1 + (s))
#define FREE_BAR(s) (4 + (s))

__global__ __launch_bounds__(NTHR, 1)
void hc_mma_kernel(const float* __restrict__ A, float* __restrict__ out) {
    extern __shared__ char sm[];
    const int tid  = threadIdx.x;
    const int wid  = tid >> 5, lane = tid & 31;
    const int row0 = blockIdx.x * 128;
    const uint32_t smu = smem_u32(sm);

    if (wid < NCONS) {
        // =============================== CONSUMER ===========================
        // 4 M-warps x 4 N-warps; warp tile 32 x 32 (2 x 16-col groups)
        const int m0 = (wid & 3) * 32;
        const int n0 = (wid >> 2) * 32;
        const int frow = lane & 15;
        const int u16  = lane >> 4;

        float acc[2][4][4];
        #pragma unroll
        for (int mt = 0; mt < 2; mt++)
            #pragma unroll
            for (int j = 0; j < 4; j++)
                #pragma unroll
                for (int e = 0; e < 4; e++) acc[mt][j][e] = 0.0f;

        int s = 0;
        for (int ck = 0; ck < 32; ck++) {
            BAR_SYNC(FULL_BAR(s));
            uint32_t stg  = smu + s * STAGE;
            uint32_t aHiB = stg + AHI_OFF;
            uint32_t bHiB = stg + BHI_OFF;

            #pragma unroll
            for (int ks = 0; ks < 4; ks++) {
                const int u0 = ks * 2 + u16;
                uint32_t ah[2][4], al[2][4];
                #pragma unroll
                for (int mt = 0; mt < 2; mt++) {
                    int row = m0 + mt * 16 + frow;
                    uint32_t ad = aHiB + row * 128 + SWZ16(row, u0);
                    LDSM_X4(ah[mt][0], ah[mt][1], ah[mt][2], ah[mt][3], ad);
                    LDSM_X4(al[mt][0], al[mt][1], al[mt][2], al[mt][3],
                            ad + (ALO_OFF - AHI_OFF));
                }
                #pragma unroll
                for (int g = 0; g < 2; g++) {
                    int row = n0 + g * 16 + frow;
                    uint32_t bd = bHiB + row * 128 + SWZ16(row, u0);
                    uint32_t h0, h1, h2, h3, l0, l1, l2, l3;
                    LDSM_X4(h0, h1, h2, h3, bd);
                    LDSM_X4(l0, l1, l2, l3, bd + (BLO_OFF - BHI_OFF));
                    #pragma unroll
                    for (int mt = 0; mt < 2; mt++) {
                        MMA_BF16(acc[mt][2*g],   ah[mt], h0, h2);
                        MMA_BF16(acc[mt][2*g+1], ah[mt], h1, h3);
                    }
                    #pragma unroll
                    for (int mt = 0; mt < 2; mt++) {
                        MMA_BF16(acc[mt][2*g],   ah[mt], l0, l2);
                        MMA_BF16(acc[mt][2*g+1], ah[mt], l1, l3);
                    }
                    #pragma unroll
                    for (int mt = 0; mt < 2; mt++) {
                        MMA_BF16(acc[mt][2*g],   al[mt], h0, h2);
                        MMA_BF16(acc[mt][2*g+1], al[mt], h1, h3);
                    }
                }
            }
            BAR_ARRIVE(FREE_BAR(s));
            if (++s == NSTAGE) s = 0;
        }

        // restage bottom logits (+bias) into stage0 only ([128][128] f32 = 64KB;
        // stage1 may still be in use by other consumers finishing ck=31)
        float* Ls = (float*)sm;
        const int rr = lane >> 2;
        const int cc = (lane & 3) * 2;
        #pragma unroll
        for (int mt = 0; mt < 2; mt++)
            #pragma unroll
            for (int j = 0; j < 4; j++) {
                int r = m0 + mt * 16 + rr;
                int c = n0 + j * 8 + cc;
                float b0 = g_bias[c], b1 = g_bias[c + 1];
                Ls[r * LPITCH + c]           = acc[mt][j][0] + b0;
                Ls[r * LPITCH + c + 1]       = acc[mt][j][1] + b1;
                Ls[(r + 8) * LPITCH + c]     = acc[mt][j][2] + b0;
                Ls[(r + 8) * LPITCH + c + 1] = acc[mt][j][3] + b1;
            }
    } else {
        // =============================== PRODUCER ===========================
        const int tp = tid - NCONS * 32;          // 0..127, one A row each
        const float* aRow = A + (size_t)(row0 + tp) * D_K;

        float4 av0[8], av1[8];                    // two 32-k halves
        float gacc[8];
        #pragma unroll
        for (int t = 0; t < 8; t++) gacc[t] = 0.0f;

        auto ldgA = [&](int kt, float4* av, int h) {
            #pragma unroll
            for (int q = 0; q < 8; q++)
                av[q] = *(const float4*)(aRow + kt + h * 32 + q * 4);
        };
        auto cpB = [&](int kt, int s) {
            uint32_t bBase = smu + s * STAGE + BHI_OFF;
            #pragma unroll
            for (int p = 0; p < 16; p++) {
                int i = tp + p * 128;               // 0..2047 exactly
                int half = (i >= 1024) ? 1 : 0;
                int j = i - half * 1024;
                int n = j >> 3, seg = j & 7;
                const __nv_bfloat16* src =
                    (half ? g_Bl : g_Bh) + (size_t)n * D_K + kt + seg * 8;
                uint32_t dst = bBase + half * (BLO_OFF - BHI_OFF)
                             + n * 128 + SWZ16(n, seg);
                CP16(dst, src);
            }
        };
        // store one 32-k half of A (hi/lo split) + fp32 gate FMA for that half
        auto stsA_gate = [&](int s, int h, const float4* av, int kt) {
            char* d = sm + s * STAGE + tp * 128;
            #pragma unroll
            for (int q = 0; q < 4; q++) {           // 16B unit q within half
                uint32_t hi[4], lo[4];
                split2(av[2*q].x,   av[2*q].y,   hi[0], lo[0]);
                split2(av[2*q].z,   av[2*q].w,   hi[1], lo[1]);
                split2(av[2*q+1].x, av[2*q+1].y, hi[2], lo[2]);
                split2(av[2*q+1].z, av[2*q+1].w, hi[3], lo[3]);
                uint32_t sw = SWZ16(tp, h * 4 + q);
                *(uint4*)(d + AHI_OFF + sw) = make_uint4(hi[0], hi[1], hi[2], hi[3]);
                *(uint4*)(d + ALO_OFF + sw) = make_uint4(lo[0], lo[1], lo[2], lo[3]);

                // gate: 8 k-values of this q x 8 top labels, uniform __ldg W
                const float4* wp = (const float4*)
                    (g_topWt + ((size_t)(kt + h * 32 + q * 8)) * 8);
                const float* a8 = (const float*)&av[2*q];
                #pragma unroll
                for (int j = 0; j < 8; j++) {
                    float a = a8[j];
                    float4 w0 = __ldg(&wp[j * 2]);
                    float4 w1 = __ldg(&wp[j * 2 + 1]);
                    gacc[0] = fmaf(a, w0.x, gacc[0]);
                    gacc[1] = fmaf(a, w0.y, gacc[1]);
                    gacc[2] = fmaf(a, w0.z, gacc[2]);
                    gacc[3] = fmaf(a, w0.w, gacc[3]);
                    gacc[4] = fmaf(a, w1.x, gacc[4]);
                    gacc[5] = fmaf(a, w1.y, gacc[5]);
                    gacc[6] = fmaf(a, w1.z, gacc[6]);
                    gacc[7] = fmaf(a, w1.w, gacc[7]);
                }
            }
        };

        // prologue: fill all 3 stages
        #pragma unroll
        for (int ck = 0; ck < 3; ck++) {
            int kt = ck * 64;
            ldgA(kt, av0, 0);
            ldgA(kt, av1, 1);
            cpB(kt, ck);
            stsA_gate(ck, 0, av0, kt);
            stsA_gate(ck, 1, av1, kt);
            CP_COMMIT(); CP_WAIT0();
            BAR_ARRIVE(FULL_BAR(ck));
        }

        int s = 0;
        for (int ck = 3; ck < 32; ck++) {
            int kt = ck * 64;
            ldgA(kt, av0, 0);              // prefetch across the FREE wait
            BAR_SYNC(FREE_BAR(s));
            ldgA(kt, av1, 1);              // in flight behind h0 processing
            cpB(kt, s);
            stsA_gate(s, 0, av0, kt);
            stsA_gate(s, 1, av1, kt);
            CP_COMMIT(); CP_WAIT0();
            BAR_ARRIVE(FULL_BAR(s));
            if (++s == NSTAGE) s = 0;
        }

        // publish fp32-exact gate logits
        float* topL = (float*)(sm + TOPL_OFF);
        #pragma unroll
        for (int t = 0; t < 8; t++) topL[tp * 8 + t] = gacc[t];
    }

    __syncthreads();

    // ---- epilogue: 128 rows x 8 top-labels = 1024 tasks ----
    const float* Ls   = (const float*)sm;
    const float* topL = (const float*)(sm + TOPL_OFF);
    #pragma unroll
    for (int p = 0; p < 2; p++) {
        int task = tid + p * NTHR;
        if (task < 1024) {
            int r = task >> 3, t = task & 7;
            const float* Lr = Ls + r * LPITCH;

            float gate = 1.0f / (1.0f + __expf(-(topL[r * 8 + t] + g_bias[128 + t])));

            float l[16], mx = -1e30f;
            #pragma unroll
            for (int c = 0; c < 16; c++) {
                l[c] = Lr[t * 16 + c];
                mx = fmaxf(mx, l[c]);
            }
            float ssum = 0.0f;
            #pragma unroll
            for (int c = 0; c < 16; c++) { l[c] = __expf(l[c] - mx); ssum += l[c]; }
            float sc = gate / ssum;

            float* op = out + (size_t)(row0 + r) * 128 + t * 16;
            #pragma unroll
            for (int q = 0; q < 4; q++) {
                float4 v;
                v.x = l[q * 4 + 0] * sc;
                v.y = l[q * 4 + 1] * sc;
                v.z = l[q * 4 + 2] * sc;
                v.w = l[q * 4 + 3] * sc;
                ((float4*)op)[q] = v;
            }
        }
    }
}

// ---------------------------------------------------------------------------
extern "C" void kernel_launch(void* const* d_in, const int* in_sizes, int n_in,
                              void* d_out, int out_size) {
    const float* features = (const float*)d_in[0];
    const float* topW     = (const float*)d_in[1];
    const float* topb     = (const float*)d_in[2];
    const float* botW     = (const float*)d_in[3];
    const float* botb     = (const float*)d_in[4];
    float* out = (float*)d_out;

    cudaFuncSetAttribute(hc_mma_kernel,
                         cudaFuncAttributeMaxDynamicSharedMemorySize, SMEM_DYN);

    pack_kernel<<<(128 * D_K + 255) / 256, 256>>>(topW, topb, botW, botb);
    hc_mma_kernel<<<16384 / 128, NTHR, SMEM_DYN>>>(features, out);
}

// round 17
// speedup vs baseline: 1.9068x; 1.9068x over previous
#include <cuda_runtime.h>
#include <cuda_bf16.h>
#include <stdint.h>
#include <math.h>

// ---------------------------------------------------------------------------
// HierarchicalClassifier, warp-specialized bf16 HMMA on sm_103a.
//   logits[16384,136] = A[16384,2048] @ Wpacked[2048,136] via 3-term bf16
//   hi/lo split (Ah*Bh + Ah*Bl + Al*Bh). Cols: [0,128) bottom, [128,136) gate.
// R15: MMA N = 136 exactly (no pad). 16 consumers 4Mx4N (tiles 32x32 x3 +
//      32x40 w/ x2 tail) + 4 pure-fill producers (R13-proven), 3-stage
//      XOR-swizzled pipeline. Driven by empirical law: mma.sync rate is
//      ~1/13.7 cyc/SMSP invariant -> minimize MMA count, nothing else matters.
// ---------------------------------------------------------------------------

#define D_K   2048
#define N_W   136

__device__ __nv_bfloat16 g_Bh[N_W * D_K];   // [n][k] K-major, bf16 hi
__device__ __nv_bfloat16 g_Bl[N_W * D_K];   // bf16 lo
__device__ float         g_bias[N_W];       // [0,128) bottom, [128,136) gate

// ---------------------------------------------------------------------------
__global__ void pack_kernel(const float* __restrict__ topW,
                            const float* __restrict__ topb,
                            const float* __restrict__ botW,
                            const float* __restrict__ botb) {
    int idx = blockIdx.x * blockDim.x + threadIdx.x;
    if (idx < N_W * D_K) {
        int n = idx / D_K, k = idx - n * D_K;
        float v;
        if (n < 128) {
            int t = n >> 4, c = n & 15;
            v = botW[((size_t)t * D_K + k) * 16 + c];
        } else {
            v = topW[(n - 128) * D_K + k];
        }
        __nv_bfloat16 hi = __float2bfloat16(v);
        g_Bh[idx] = hi;
        g_Bl[idx] = __float2bfloat16(v - __bfloat162float(hi));
    }
    if (idx < N_W)
        g_bias[idx] = (idx < 128) ? botb[idx] : topb[idx - 128];
}

// ---------------------------------------------------------------------------
__device__ __forceinline__ uint32_t smem_u32(const void* p) {
    uint32_t a;
    asm("{ .reg .u64 t; cvta.to.shared.u64 t, %1; cvt.u32.u64 %0, t; }"
        : "=r"(a) : "l"(p));
    return a;
}

#define LDSM_X4(r0, r1, r2, r3, addr) \
    asm volatile("ldmatrix.sync.aligned.m8n8.x4.shared.b16 {%0,%1,%2,%3}, [%4];" \
        : "=r"(r0), "=r"(r1), "=r"(r2), "=r"(r3) : "r"(addr))

#define LDSM_X2(r0, r1, addr) \
    asm volatile("ldmatrix.sync.aligned.m8n8.x2.shared.b16 {%0,%1}, [%2];" \
        : "=r"(r0), "=r"(r1) : "r"(addr))

#define MMA_BF16(d, a, b0, b1) \
    asm volatile("mma.sync.aligned.m16n8k16.row.col.f32.bf16.bf16.f32 " \
        "{%0,%1,%2,%3}, {%4,%5,%6,%7}, {%8,%9}, {%0,%1,%2,%3};" \
        : "+f"((d)[0]), "+f"((d)[1]), "+f"((d)[2]), "+f"((d)[3]) \
        : "r"((a)[0]), "r"((a)[1]), "r"((a)[2]), "r"((a)[3]), \
          "r"(b0), "r"(b1))

#define CP16(dst, src) \
    asm volatile("cp.async.cg.shared.global [%0], [%1], 16;" \
        :: "r"(dst), "l"(src) : "memory")
#define CP_COMMIT() asm volatile("cp.async.commit_group;" ::: "memory")
#define CP_WAIT0()  asm volatile("cp.async.wait_group 0;" ::: "memory")

#define BAR_SYNC(id)   asm volatile("bar.sync %0, 640;"   :: "r"(id) : "memory")
#define BAR_ARRIVE(id) asm volatile("bar.arrive %0, 640;" :: "r"(id) : "memory")

__device__ __forceinline__ void split2(float v0, float v1, uint32_t& h, uint32_t& l) {
    uint32_t hp;
    asm("cvt.rn.bf16x2.f32 %0, %1, %2;" : "=r"(hp) : "f"(v1), "f"(v0));
    float h0 = __uint_as_float(hp << 16);
    float h1 = __uint_as_float(hp & 0xffff0000u);
    uint32_t lp;
    asm("cvt.rn.bf16x2.f32 %0, %1, %2;" : "=r"(lp) : "f"(v1 - h1), "f"(v0 - h0));
    h = hp; l = lp;
}

// XOR swizzle: 16B unit u of a 128B row -> u ^ (row & 7)
#define SWZ16(row, u) ((uint32_t)(((u) ^ ((row) & 7)) << 4))

// ---------------------------------------------------------------------------
// Stage (pitch 128B): Ahi @0 (16384) | Alo @16384 | Bhi @32768 (136*128=17408)
// | Blo @50176 (17408).  STAGE = 67584, 3 stages = 202752.
// topL side buffer (128 x 8 f32) after stage2. Restage Ls = [128][128] f32
// = 65536 B, fits entirely inside stage0.
// ---------------------------------------------------------------------------
constexpr int AHI_OFF  = 0;
constexpr int ALO_OFF  = 16384;
constexpr int BHI_OFF  = 32768;
constexpr int BLO_OFF  = 50176;
constexpr int STAGE    = 67584;
constexpr int NSTAGE   = 3;
constexpr int TOPL_OFF = NSTAGE * STAGE;           // 202752
constexpr int SMEM_DYN = TOPL_OFF + 128 * 8 * 4;   // 206848

constexpr int NTHR  = 640;     // 16 consumer warps + 4 producer warps
constexpr int NCONS = 16;
constexpr int LPITCH = 128;

#define FULL_BAR(s) (1 + (s))
#define FREE_BAR(s) (4 + (s))

__global__ __launch_bounds__(NTHR, 1)
void hc_mma_kernel(const float* __restrict__ A, float* __restrict__ out) {
    extern __shared__ char sm[];
    const int tid  = threadIdx.x;
    const int wid  = tid >> 5, lane = tid & 31;
    const int row0 = blockIdx.x * 128;
    const uint32_t smu = smem_u32(sm);

    if (wid < NCONS) {
        // =============================== CONSUMER ===========================
        // 4 M-warps x 4 N-warps. m0 = (wid&3)*32. n0 = (wid>>2)*32;
        // N-warps 0..2: 32 cols (2 x4-groups); N-warp 3: 40 cols (2 groups + x2 tail)
        const int m0 = (wid & 3) * 32;
        const int nw = wid >> 2;
        const int n0 = nw * 32;
        const bool tailw = (nw == 3);
        const int frow = lane & 15;
        const int u16  = lane >> 4;
        const int xrow = lane & 7;             // x2 tail lane mapping
        const int xu   = (lane >> 3) & 1;

        float acc[2][5][4];   // slot 4 = gate tail (last N-warp only)
        #pragma unroll
        for (int mt = 0; mt < 2; mt++)
            #pragma unroll
            for (int j = 0; j < 5; j++)
                #pragma unroll
                for (int e = 0; e < 4; e++) acc[mt][j][e] = 0.0f;

        int s = 0;
        for (int ck = 0; ck < 32; ck++) {
            BAR_SYNC(FULL_BAR(s));
            uint32_t stg  = smu + s * STAGE;
            uint32_t aHiB = stg + AHI_OFF;
            uint32_t bHiB = stg + BHI_OFF;

            #pragma unroll
            for (int ks = 0; ks < 4; ks++) {
                const int u0 = ks * 2 + u16;
                uint32_t ah[2][4], al[2][4];
                #pragma unroll
                for (int mt = 0; mt < 2; mt++) {
                    int row = m0 + mt * 16 + frow;
                    uint32_t ad = aHiB + row * 128 + SWZ16(row, u0);
                    LDSM_X4(ah[mt][0], ah[mt][1], ah[mt][2], ah[mt][3], ad);
                    LDSM_X4(al[mt][0], al[mt][1], al[mt][2], al[mt][3],
                            ad + (ALO_OFF - AHI_OFF));
                }
                #pragma unroll
                for (int g = 0; g < 2; g++) {
                    int row = n0 + g * 16 + frow;
                    uint32_t bd = bHiB + row * 128 + SWZ16(row, u0);
                    uint32_t h0, h1, h2, h3, l0, l1, l2, l3;
                    LDSM_X4(h0, h1, h2, h3, bd);
                    LDSM_X4(l0, l1, l2, l3, bd + (BLO_OFF - BHI_OFF));
                    #pragma unroll
                    for (int mt = 0; mt < 2; mt++) {
                        MMA_BF16(acc[mt][2*g],   ah[mt], h0, h2);
                        MMA_BF16(acc[mt][2*g+1], ah[mt], h1, h3);
                    }
                    #pragma unroll
                    for (int mt = 0; mt < 2; mt++) {
                        MMA_BF16(acc[mt][2*g],   ah[mt], l0, l2);
                        MMA_BF16(acc[mt][2*g+1], ah[mt], l1, l3);
                    }
                    #pragma unroll
                    for (int mt = 0; mt < 2; mt++) {
                        MMA_BF16(acc[mt][2*g],   al[mt], h0, h2);
                        MMA_BF16(acc[mt][2*g+1], al[mt], h1, h3);
                    }
                }
                if (tailw) {   // gate tail: B rows 128..135
                    int row = 128 + xrow;
                    int u = ks * 2 + xu;
                    uint32_t bd = bHiB + row * 128 + SWZ16(row, u);
                    uint32_t xh0, xh1, xl0, xl1;
                    LDSM_X2(xh0, xh1, bd);
                    LDSM_X2(xl0, xl1, bd + (BLO_OFF - BHI_OFF));
                    #pragma unroll
                    for (int mt = 0; mt < 2; mt++) MMA_BF16(acc[mt][4], ah[mt], xh0, xh1);
                    #pragma unroll
                    for (int mt = 0; mt < 2; mt++) MMA_BF16(acc[mt][4], ah[mt], xl0, xl1);
                    #pragma unroll
                    for (int mt = 0; mt < 2; mt++) MMA_BF16(acc[mt][4], al[mt], xh0, xh1);
                }
            }
            BAR_ARRIVE(FREE_BAR(s));
            if (++s == NSTAGE) s = 0;
        }

        // restage: bottom cols -> Ls (stage0, [128][128] f32 = exactly 64KB),
        // gate cols -> topL side buffer. Safe: all consumers passed ck=31's
        // FULL sync (so ck<=30 stage0 reads done); ck=31 reads stage1 only;
        // topL is outside all stages.
        float* Ls   = (float*)sm;
        float* topL = (float*)(sm + TOPL_OFF);
        const int rr = lane >> 2;
        const int cc = (lane & 3) * 2;
        #pragma unroll
        for (int mt = 0; mt < 2; mt++) {
            #pragma unroll
            for (int j = 0; j < 4; j++) {
                int r = m0 + mt * 16 + rr;
                int c = n0 + j * 8 + cc;
                float b0 = g_bias[c], b1 = g_bias[c + 1];
                Ls[r * LPITCH + c]           = acc[mt][j][0] + b0;
                Ls[r * LPITCH + c + 1]       = acc[mt][j][1] + b1;
                Ls[(r + 8) * LPITCH + c]     = acc[mt][j][2] + b0;
                Ls[(r + 8) * LPITCH + c + 1] = acc[mt][j][3] + b1;
            }
            if (tailw) {
                int r = m0 + mt * 16 + rr;
                float b0 = g_bias[128 + cc], b1 = g_bias[128 + cc + 1];
                topL[r * 8 + cc]           = acc[mt][4][0] + b0;
                topL[r * 8 + cc + 1]       = acc[mt][4][1] + b1;
                topL[(r + 8) * 8 + cc]     = acc[mt][4][2] + b0;
                topL[(r + 8) * 8 + cc + 1] = acc[mt][4][3] + b1;
            }
        }
    } else {
        // =============================== PRODUCER (pure fill, R13-proven) ===
        const int tp = tid - NCONS * 32;          // 0..127, one A row each
        const float* aRow = A + (size_t)(row0 + tp) * D_K;

        float4 av[16];
        auto ldgA = [&](int kt) {
            #pragma unroll
            for (int q = 0; q < 16; q++)
                av[q] = *(const float4*)(aRow + kt + q * 4);
        };
        auto cpB = [&](int kt, int s) {
            uint32_t bBase = smu + s * STAGE + BHI_OFF;
            #pragma unroll
            for (int p = 0; p < 17; p++) {
                int i = tp + p * 128;               // 0..2175 exactly (136*8*2)
                int half = (i >= 1088) ? 1 : 0;
                int j = i - half * 1088;
                int n = j >> 3, seg = j & 7;
                const __nv_bfloat16* src =
                    (half ? g_Bl : g_Bh) + (size_t)n * D_K + kt + seg * 8;
                uint32_t dst = bBase + half * (BLO_OFF - BHI_OFF)
                             + n * 128 + SWZ16(n, seg);
                CP16(dst, src);
            }
        };
        auto stsA = [&](int s) {
            char* d = sm + s * STAGE + tp * 128;
            #pragma unroll
            for (int q = 0; q < 8; q++) {           // all 8 16B units per row
                uint32_t hi[4], lo[4];
                split2(av[2*q].x,   av[2*q].y,   hi[0], lo[0]);
                split2(av[2*q].z,   av[2*q].w,   hi[1], lo[1]);
                split2(av[2*q+1].x, av[2*q+1].y, hi[2], lo[2]);
                split2(av[2*q+1].z, av[2*q+1].w, hi[3], lo[3]);
                uint32_t sw = SWZ16(tp, q);
                *(uint4*)(d + AHI_OFF + sw) = make_uint4(hi[0], hi[1], hi[2], hi[3]);
                *(uint4*)(d + ALO_OFF + sw) = make_uint4(lo[0], lo[1], lo[2], lo[3]);
            }
        };

        // prologue: fill all 3 stages
        #pragma unroll
        for (int ck = 0; ck < 3; ck++) {
            ldgA(ck * 64);
            cpB(ck * 64, ck);
            stsA(ck);
            CP_COMMIT(); CP_WAIT0();
            BAR_ARRIVE(FULL_BAR(ck));
        }

        int s = 0;
        for (int ck = 3; ck < 32; ck++) {
            ldgA(ck * 64);                 // LDG in flight across the FREE wait
            BAR_SYNC(FREE_BAR(s));
            cpB(ck * 64, s);
            stsA(s);
            CP_COMMIT(); CP_WAIT0();
            BAR_ARRIVE(FULL_BAR(s));
            if (++s == NSTAGE) s = 0;
        }
    }

    __syncthreads();

    // ---- epilogue: 128 rows x 8 top-labels = 1024 tasks ----
    const float* Ls   = (const float*)sm;
    const float* topL = (const float*)(sm + TOPL_OFF);
    #pragma unroll
    for (int p = 0; p < 2; p++) {
        int task = tid + p * NTHR;
        if (task < 1024) {
            int r = task >> 3, t = task & 7;
            const float* Lr = Ls + r * LPITCH;

            float gate = 1.0f / (1.0f + __expf(-topL[r * 8 + t]));

            float l[16], mx = -1e30f;
            #pragma unroll
            for (int c = 0; c < 16; c++) {
                l[c] = Lr[t * 16 + c];
                mx = fmaxf(mx, l[c]);
            }
            float ssum = 0.0f;
            #pragma unroll
            for (int c = 0; c < 16; c++) { l[c] = __expf(l[c] - mx); ssum += l[c]; }
            float sc = gate / ssum;

            float* op = out + (size_t)(row0 + r) * 128 + t * 16;
            #pragma unroll
            for (int q = 0; q < 4; q++) {
                float4 v;
                v.x = l[q * 4 + 0] * sc;
                v.y = l[q * 4 + 1] * sc;
                v.z = l[q * 4 + 2] * sc;
                v.w = l[q * 4 + 3] * sc;
                ((float4*)op)[q] = v;
            }
        }
    }
}

// ---------------------------------------------------------------------------
extern "C" void kernel_launch(void* const* d_in, const int* in_sizes, int n_in,
                              void* d_out, int out_size) {
    const float* features = (const float*)d_in[0];
    const float* topW     = (const float*)d_in[1];
    const float* topb     = (const float*)d_in[2];
    const float* botW     = (const float*)d_in[3];
    const float* botb     = (const float*)d_in[4];
    float* out = (float*)d_out;

    cudaFuncSetAttribute(hc_mma_kernel,
                         cudaFuncAttributeMaxDynamicSharedMemorySize, SMEM_DYN);

    pack_kernel<<<(N_W * D_K + 255) / 256, 256>>>(topW, topb, botW, botb);
    hc_mma_kernel<<<16384 / 128, NTHR, SMEM_DYN>>>(features, out);
}